// round 1
// baseline (speedup 1.0000x reference)
#include <cuda_runtime.h>
#include <math.h>

// Problem shape (fixed by the reference)
#define Bb   16
#define Ss   4096
#define Dd   768
#define Hh   384
#define KTOK 40
#define Mtot (Bb * Ss)          // 65536 tokens

// ---------------------------------------------------------------------------
// Device scratch (static __device__ arrays: the allowed allocation mechanism)
// ---------------------------------------------------------------------------
__device__ float g_h[(size_t)Mtot * Hh];   // 96 MB: h = features @ W1 + b1
__device__ float g_scores[Mtot];
__device__ int   g_idx[Bb * KTOK];

// ---------------------------------------------------------------------------
// Packed f32x2 helpers (sm_100+ PTX; ptxas never auto-generates FFMA2)
// ---------------------------------------------------------------------------
__device__ __forceinline__ void fma2(unsigned long long& d,
                                     unsigned long long a,
                                     unsigned long long b) {
    asm("fma.rn.f32x2 %0, %1, %2, %0;" : "+l"(d) : "l"(a), "l"(b));
}
__device__ __forceinline__ unsigned long long splat2(float a) {
    unsigned long long r;
    asm("mov.b64 %0, {%1, %1};" : "=l"(r) : "f"(a));
    return r;
}
__device__ __forceinline__ float2 unpk2(unsigned long long v) {
    float2 r;
    asm("mov.b64 {%0, %1}, %2;" : "=f"(r.x), "=f"(r.y) : "l"(v));
    return r;
}

// ---------------------------------------------------------------------------
// Kernel 1: fp32 GEMM  h[M,H] = A[M,D] * W[D,H] + b   via FFMA2
//   Block tile 64(M) x 128(N), BK=32.  256 threads, 4x8 microtile per thread.
// ---------------------------------------------------------------------------
#define BM 64
#define BN 128
#define BK 32

__global__ void __launch_bounds__(256)
gemm_kernel(const float* __restrict__ A, const float* __restrict__ W,
            const float* __restrict__ bias) {
    __shared__ float As[BM][BK];   // natural [m][k]: float4 k-runs per row
    __shared__ float Bs[BK][BN];   // natural [k][n]: contiguous n for pair loads

    const int n0  = blockIdx.x * BN;   // x fastest -> same m-tile adjacent (L2 reuse of A)
    const int m0  = blockIdx.y * BM;
    const int tid = threadIdx.x;
    const int tx  = tid & 15;          // 16 cols of threads
    const int ty  = tid >> 4;          // 16 rows of threads
    const int row0 = ty * 4;           // 4 rows per thread
    const int col0 = tx * 8;           // 8 cols per thread (4 f32x2 pairs)

    unsigned long long acc[4][4];
    #pragma unroll
    for (int r = 0; r < 4; r++)
        #pragma unroll
        for (int p = 0; p < 4; p++) acc[r][p] = 0ull;   // bit pattern of (0.f,0.f)

    for (int k0 = 0; k0 < Dd; k0 += BK) {
        // load A tile: 64x32 = 512 float4, 2 per thread (conflict-free STS.128)
        #pragma unroll
        for (int i = 0; i < 2; i++) {
            int f  = tid + i * 256;
            int m  = f >> 3;
            int kq = f & 7;
            float4 v = *(const float4*)(A + (size_t)(m0 + m) * Dd + k0 + kq * 4);
            *(float4*)&As[m][kq * 4] = v;
        }
        // load B tile: 32x128 = 1024 float4, 4 per thread (conflict-free)
        #pragma unroll
        for (int i = 0; i < 4; i++) {
            int f  = tid + i * 256;
            int kr = f >> 5;
            int nq = f & 31;
            float4 v = *(const float4*)(W + (size_t)(k0 + kr) * Hh + n0 + nq * 4);
            *(float4*)&Bs[kr][nq * 4] = v;
        }
        __syncthreads();

        #pragma unroll
        for (int kk = 0; kk < BK; kk += 4) {
            float4 a4[4];
            #pragma unroll
            for (int r = 0; r < 4; r++)
                a4[r] = *(const float4*)&As[row0 + r][kk];
            #pragma unroll
            for (int u = 0; u < 4; u++) {
                ulonglong2 b01 = *(const ulonglong2*)&Bs[kk + u][col0];
                ulonglong2 b23 = *(const ulonglong2*)&Bs[kk + u][col0 + 4];
                #pragma unroll
                for (int r = 0; r < 4; r++) {
                    float av = (u == 0) ? a4[r].x : (u == 1) ? a4[r].y
                             : (u == 2) ? a4[r].z : a4[r].w;
                    unsigned long long aa = splat2(av);
                    fma2(acc[r][0], aa, b01.x);
                    fma2(acc[r][1], aa, b01.y);
                    fma2(acc[r][2], aa, b23.x);
                    fma2(acc[r][3], aa, b23.y);
                }
            }
        }
        __syncthreads();
    }

    // epilogue: + bias, store to g_h
    float4 bb0 = *(const float4*)(bias + n0 + col0);
    float4 bb1 = *(const float4*)(bias + n0 + col0 + 4);
    #pragma unroll
    for (int r = 0; r < 4; r++) {
        float2 c0 = unpk2(acc[r][0]);
        float2 c1 = unpk2(acc[r][1]);
        float2 c2 = unpk2(acc[r][2]);
        float2 c3 = unpk2(acc[r][3]);
        float4 o0 = make_float4(c0.x + bb0.x, c0.y + bb0.y, c1.x + bb0.z, c1.y + bb0.w);
        float4 o1 = make_float4(c2.x + bb1.x, c2.y + bb1.y, c3.x + bb1.z, c3.y + bb1.w);
        float* dst = g_h + (size_t)(m0 + row0 + r) * Hh + n0 + col0;
        *(float4*)(dst)     = o0;
        *(float4*)(dst + 4) = o1;
    }
}

// ---------------------------------------------------------------------------
// Kernel 2: per-token LayerNorm (two-pass, matches reference) + exact GELU +
//           dot(W2) + sigmoid.  One warp per token, 8 warps per block.
// ---------------------------------------------------------------------------
__global__ void __launch_bounds__(256)
score_kernel(const float* __restrict__ gamma, const float* __restrict__ beta,
             const float* __restrict__ W2,    const float* __restrict__ b2) {
    const int lane  = threadIdx.x & 31;
    const int warp  = threadIdx.x >> 5;
    const int token = blockIdx.x * 8 + warp;

    const float4* hrow = (const float4*)(g_h + (size_t)token * Hh);

    float4 v[3];
    float sum = 0.f;
    #pragma unroll
    for (int i = 0; i < 3; i++) {
        v[i] = hrow[i * 32 + lane];
        sum += v[i].x + v[i].y + v[i].z + v[i].w;
    }
    #pragma unroll
    for (int o = 16; o > 0; o >>= 1) sum += __shfl_xor_sync(0xffffffffu, sum, o);
    const float mu = sum * (1.0f / Hh);

    float sq = 0.f;
    #pragma unroll
    for (int i = 0; i < 3; i++) {
        float a = v[i].x - mu, b = v[i].y - mu, c = v[i].z - mu, d = v[i].w - mu;
        sq += a * a + b * b + c * c + d * d;
    }
    #pragma unroll
    for (int o = 16; o > 0; o >>= 1) sq += __shfl_xor_sync(0xffffffffu, sq, o);
    const float var  = sq * (1.0f / Hh);
    const float rstd = 1.0f / sqrtf(var + 1e-5f);

    float dot = 0.f;
    #pragma unroll
    for (int i = 0; i < 3; i++) {
        int f = (i * 32 + lane) * 4;
        float4 g4 = *(const float4*)(gamma + f);
        float4 be = *(const float4*)(beta + f);
        float4 w4 = *(const float4*)(W2 + f);
        float x[4] = {v[i].x, v[i].y, v[i].z, v[i].w};
        float gm[4] = {g4.x, g4.y, g4.z, g4.w};
        float bt[4] = {be.x, be.y, be.z, be.w};
        float ww[4] = {w4.x, w4.y, w4.z, w4.w};
        #pragma unroll
        for (int c = 0; c < 4; c++) {
            float xn = (x[c] - mu) * rstd * gm[c] + bt[c];
            float ge = 0.5f * xn * (1.0f + erff(xn * 0.70710678118654752f));
            dot += ge * ww[c];
        }
    }
    #pragma unroll
    for (int o = 16; o > 0; o >>= 1) dot += __shfl_xor_sync(0xffffffffu, dot, o);

    if (lane == 0) {
        float s = dot + b2[0];
        g_scores[token] = 1.0f / (1.0f + expf(-s));
    }
}

// ---------------------------------------------------------------------------
// Kernel 3: top-40 per batch, descending, ties -> lower index (jax top_k rule)
// ---------------------------------------------------------------------------
__global__ void __launch_bounds__(256)
topk_kernel() {
    __shared__ float s[Ss];
    __shared__ float rv[256];
    __shared__ int   ri[256];
    const int b = blockIdx.x;
    const int t = threadIdx.x;

    for (int i = t; i < Ss; i += 256) s[i] = g_scores[b * Ss + i];
    __syncthreads();

    for (int sel = 0; sel < KTOK; sel++) {
        float bv = -1e30f; int bi = Ss;
        for (int i = t; i < Ss; i += 256) {
            float vv = s[i];
            if (vv > bv || (vv == bv && i < bi)) { bv = vv; bi = i; }
        }
        rv[t] = bv; ri[t] = bi;
        __syncthreads();
        for (int off = 128; off > 0; off >>= 1) {
            if (t < off) {
                float ov = rv[t + off]; int oi = ri[t + off];
                if (ov > rv[t] || (ov == rv[t] && oi < ri[t])) { rv[t] = ov; ri[t] = oi; }
            }
            __syncthreads();
        }
        if (t == 0) { g_idx[b * KTOK + sel] = ri[0]; s[ri[0]] = -1e30f; }
        __syncthreads();
    }
}

// ---------------------------------------------------------------------------
// Kernel 4: gather selected tokens into d_out; append indices as float
//   (tuple outputs concatenated: tokens [B,K,D] then indices [B,K])
// ---------------------------------------------------------------------------
__global__ void __launch_bounds__(192)
gather_kernel(const float* __restrict__ features, float* __restrict__ out,
              long long out_size) {
    const int blk = blockIdx.x;          // b*40 + k
    const int b   = blk / KTOK;
    const int tok = g_idx[blk];
    const int t   = threadIdx.x;         // 192 threads, 1 float4 each

    long long base = (long long)blk * Dd;
    if (base + (t + 1) * 4 <= out_size) {
        const float4* src = (const float4*)(features + ((size_t)b * Ss + tok) * Dd);
        float4* dst = (float4*)(out + base);
        dst[t] = src[t];
    }
    if (t == 0) {
        long long pos = (long long)Bb * KTOK * Dd + blk;
        if (pos < out_size) out[pos] = (float)tok;
    }
}

__global__ void fill_zero_kernel(float* __restrict__ out, long long start, long long end) {
    long long i = start + blockIdx.x * (long long)blockDim.x + threadIdx.x;
    if (i < end) out[i] = 0.f;
}

// ---------------------------------------------------------------------------
extern "C" void kernel_launch(void* const* d_in, const int* in_sizes, int n_in,
                              void* d_out, int out_size) {
    const float* features = (const float*)d_in[0];
    const float* W1       = (const float*)d_in[1];
    const float* b1       = (const float*)d_in[2];
    const float* ln_gamma = (const float*)d_in[3];
    const float* ln_beta  = (const float*)d_in[4];
    const float* W2       = (const float*)d_in[5];
    const float* b2       = (const float*)d_in[6];
    float* out = (float*)d_out;

    // 1) h = features @ W1 + b1   (grid.x = N tiles so same-m blocks adjacent)
    dim3 ggrid(Hh / BN, Mtot / BM);   // (3, 1024)
    gemm_kernel<<<ggrid, 256>>>(features, W1, b1);

    // 2) LN + GELU + W2 + sigmoid -> scores
    score_kernel<<<Mtot / 8, 256>>>(ln_gamma, ln_beta, W2, b2);

    // 3) top-40 per batch
    topk_kernel<<<Bb, 256>>>();

    // 4) gather + indices
    gather_kernel<<<Bb * KTOK, 192>>>(features, out, (long long)out_size);

    // zero any tail beyond (tokens + indices) so no poison survives
    long long written = (long long)Bb * KTOK * Dd + (long long)Bb * KTOK;
    if ((long long)out_size > written) {
        long long n = (long long)out_size - written;
        int blocks = (int)((n + 255) / 256);
        fill_zero_kernel<<<blocks, 256>>>(out, written, (long long)out_size);
    }
}

// round 2
// speedup vs baseline: 1.1437x; 1.1437x over previous
#include <cuda_runtime.h>
#include <math.h>

// Problem shape (fixed by the reference)
#define Bb   16
#define Ss   4096
#define Dd   768
#define Hh   384
#define KTOK 40
#define Mtot (Bb * Ss)          // 65536 tokens

// ---------------------------------------------------------------------------
// Device scratch
// ---------------------------------------------------------------------------
__device__ float g_h[(size_t)Mtot * Hh];   // 96 MB: h = features @ W1 + b1
__device__ float g_scores[Mtot];
__device__ int   g_idx[Bb * KTOK];

// ---------------------------------------------------------------------------
// Packed f32x2 helpers (sm_100+ PTX; ptxas never auto-generates FFMA2)
// ---------------------------------------------------------------------------
__device__ __forceinline__ void fma2(unsigned long long& d,
                                     unsigned long long a,
                                     unsigned long long b) {
    asm("fma.rn.f32x2 %0, %1, %2, %0;" : "+l"(d) : "l"(a), "l"(b));
}
__device__ __forceinline__ unsigned long long splat2(float a) {
    unsigned long long r;
    asm("mov.b64 %0, {%1, %1};" : "=l"(r) : "f"(a));
    return r;
}
__device__ __forceinline__ float2 unpk2(unsigned long long v) {
    float2 r;
    asm("mov.b64 {%0, %1}, %2;" : "=f"(r.x), "=f"(r.y) : "l"(v));
    return r;
}

// ---------------------------------------------------------------------------
// Kernel 1: fp32 GEMM  h[M,H] = A[M,D] * W[D,H] + b   via FFMA2
//   Block tile 128x128, BK=16, 256 threads, 8x8 microtile, double-buffered.
//   Per-thread columns split as [tx*4, tx*4+4) and [64+tx*4, ...) so every
//   B LDS.128 phase is a contiguous 128B run (conflict-free).
// ---------------------------------------------------------------------------
#define BM 128
#define BN 128
#define BK 16

__global__ void __launch_bounds__(256)
gemm_kernel(const float* __restrict__ A, const float* __restrict__ W,
            const float* __restrict__ bias) {
    __shared__ float As[2][BM][BK];
    __shared__ float Bs[2][BK][BN];

    const int n0  = blockIdx.x * BN;
    const int m0  = blockIdx.y * BM;
    const int tid = threadIdx.x;
    const int tx  = tid & 15;
    const int ty  = tid >> 4;
    const int row0 = ty * 8;       // 8 rows per thread
    const int colA = tx * 4;       // first 4-col group
    const int colB = 64 + tx * 4;  // second 4-col group

    // ---- global load lane assignments (2 float4 per thread per tile) ----
    // A tile: 128x16 = 512 float4; element f: m = f>>2, kq = f&3
    const int fa0 = tid, fa1 = tid + 256;
    const int am0 = fa0 >> 2, ak0 = (fa0 & 3) * 4;
    const int am1 = fa1 >> 2, ak1 = (fa1 & 3) * 4;
    const float* Ag0 = A + (size_t)(m0 + am0) * Dd + ak0;
    const float* Ag1 = A + (size_t)(m0 + am1) * Dd + ak1;
    // B tile: 16x128 = 512 float4; element f: kr = f>>5, nq = f&31
    const int bk0 = fa0 >> 5, bn0c = (fa0 & 31) * 4;
    const int bk1 = fa1 >> 5, bn1c = (fa1 & 31) * 4;
    const float* Bg0 = W + (size_t)bk0 * Hh + n0 + bn0c;
    const float* Bg1 = W + (size_t)bk1 * Hh + n0 + bn1c;

    // ---- preload tile 0 ----
    {
        float4 a0 = *(const float4*)Ag0;
        float4 a1 = *(const float4*)Ag1;
        float4 b0 = *(const float4*)Bg0;
        float4 b1 = *(const float4*)Bg1;
        *(float4*)&As[0][am0][ak0] = a0;
        *(float4*)&As[0][am1][ak1] = a1;
        *(float4*)&Bs[0][bk0][bn0c] = b0;
        *(float4*)&Bs[0][bk1][bn1c] = b1;
    }

    unsigned long long acc[8][4];
    #pragma unroll
    for (int r = 0; r < 8; r++)
        #pragma unroll
        for (int p = 0; p < 4; p++) acc[r][p] = 0ull;

    int buf = 0;
    for (int k0 = 0; k0 < Dd; k0 += BK) {
        __syncthreads();   // tile[buf] ready; prior reads of buf^1 done

        // prefetch next tile into registers
        float4 na0, na1, nb0, nb1;
        const bool more = (k0 + BK) < Dd;
        if (more) {
            na0 = *(const float4*)(Ag0 + k0 + BK);
            na1 = *(const float4*)(Ag1 + k0 + BK);
            nb0 = *(const float4*)(Bg0 + (size_t)(k0 + BK) * Hh);
            nb1 = *(const float4*)(Bg1 + (size_t)(k0 + BK) * Hh);
        }

        // compute on tile[buf]
        #pragma unroll
        for (int kk = 0; kk < BK; kk += 4) {
            float4 a4[8];
            #pragma unroll
            for (int r = 0; r < 8; r++)
                a4[r] = *(const float4*)&As[buf][row0 + r][kk];
            #pragma unroll
            for (int u = 0; u < 4; u++) {
                ulonglong2 bA = *(const ulonglong2*)&Bs[buf][kk + u][colA];
                ulonglong2 bB = *(const ulonglong2*)&Bs[buf][kk + u][colB];
                #pragma unroll
                for (int r = 0; r < 8; r++) {
                    float av = (u == 0) ? a4[r].x : (u == 1) ? a4[r].y
                             : (u == 2) ? a4[r].z : a4[r].w;
                    unsigned long long aa = splat2(av);
                    fma2(acc[r][0], aa, bA.x);
                    fma2(acc[r][1], aa, bA.y);
                    fma2(acc[r][2], aa, bB.x);
                    fma2(acc[r][3], aa, bB.y);
                }
            }
        }

        if (more) {
            *(float4*)&As[buf ^ 1][am0][ak0] = na0;
            *(float4*)&As[buf ^ 1][am1][ak1] = na1;
            *(float4*)&Bs[buf ^ 1][bk0][bn0c] = nb0;
            *(float4*)&Bs[buf ^ 1][bk1][bn1c] = nb1;
        }
        buf ^= 1;
    }

    // epilogue: + bias, store to g_h
    float4 bbA = *(const float4*)(bias + n0 + colA);
    float4 bbB = *(const float4*)(bias + n0 + colB);
    #pragma unroll
    for (int r = 0; r < 8; r++) {
        float2 c0 = unpk2(acc[r][0]);
        float2 c1 = unpk2(acc[r][1]);
        float2 c2 = unpk2(acc[r][2]);
        float2 c3 = unpk2(acc[r][3]);
        float4 oA = make_float4(c0.x + bbA.x, c0.y + bbA.y, c1.x + bbA.z, c1.y + bbA.w);
        float4 oB = make_float4(c2.x + bbB.x, c2.y + bbB.y, c3.x + bbB.z, c3.y + bbB.w);
        float* dst = g_h + (size_t)(m0 + row0 + r) * Hh + n0;
        *(float4*)(dst + colA) = oA;
        *(float4*)(dst + colB) = oB;
    }
}

// ---------------------------------------------------------------------------
// Kernel 2: per-token LayerNorm (two-pass, matches reference) + exact GELU +
//           dot(W2) + sigmoid.  One warp per token, 8 warps per block.
// ---------------------------------------------------------------------------
__global__ void __launch_bounds__(256)
score_kernel(const float* __restrict__ gamma, const float* __restrict__ beta,
             const float* __restrict__ W2,    const float* __restrict__ b2) {
    const int lane  = threadIdx.x & 31;
    const int warp  = threadIdx.x >> 5;
    const int token = blockIdx.x * 8 + warp;

    const float4* hrow = (const float4*)(g_h + (size_t)token * Hh);

    float4 v[3];
    float sum = 0.f;
    #pragma unroll
    for (int i = 0; i < 3; i++) {
        v[i] = hrow[i * 32 + lane];
        sum += v[i].x + v[i].y + v[i].z + v[i].w;
    }
    #pragma unroll
    for (int o = 16; o > 0; o >>= 1) sum += __shfl_xor_sync(0xffffffffu, sum, o);
    const float mu = sum * (1.0f / Hh);

    float sq = 0.f;
    #pragma unroll
    for (int i = 0; i < 3; i++) {
        float a = v[i].x - mu, b = v[i].y - mu, c = v[i].z - mu, d = v[i].w - mu;
        sq += a * a + b * b + c * c + d * d;
    }
    #pragma unroll
    for (int o = 16; o > 0; o >>= 1) sq += __shfl_xor_sync(0xffffffffu, sq, o);
    const float var  = sq * (1.0f / Hh);
    const float rstd = 1.0f / sqrtf(var + 1e-5f);

    float dot = 0.f;
    #pragma unroll
    for (int i = 0; i < 3; i++) {
        int f = (i * 32 + lane) * 4;
        float4 g4 = *(const float4*)(gamma + f);
        float4 be = *(const float4*)(beta + f);
        float4 w4 = *(const float4*)(W2 + f);
        float x[4] = {v[i].x, v[i].y, v[i].z, v[i].w};
        float gm[4] = {g4.x, g4.y, g4.z, g4.w};
        float bt[4] = {be.x, be.y, be.z, be.w};
        float ww[4] = {w4.x, w4.y, w4.z, w4.w};
        #pragma unroll
        for (int c = 0; c < 4; c++) {
            float xn = (x[c] - mu) * rstd * gm[c] + bt[c];
            float ge = 0.5f * xn * (1.0f + erff(xn * 0.70710678118654752f));
            dot += ge * ww[c];
        }
    }
    #pragma unroll
    for (int o = 16; o > 0; o >>= 1) dot += __shfl_xor_sync(0xffffffffu, dot, o);

    if (lane == 0) {
        float s = dot + b2[0];
        g_scores[token] = 1.0f / (1.0f + expf(-s));
    }
}

// ---------------------------------------------------------------------------
// Kernel 3: top-40 per batch, descending, ties -> lower index (jax top_k rule)
// ---------------------------------------------------------------------------
__global__ void __launch_bounds__(256)
topk_kernel() {
    __shared__ float s[Ss];
    __shared__ float rv[256];
    __shared__ int   ri[256];
    const int b = blockIdx.x;
    const int t = threadIdx.x;

    for (int i = t; i < Ss; i += 256) s[i] = g_scores[b * Ss + i];
    __syncthreads();

    for (int sel = 0; sel < KTOK; sel++) {
        float bv = -1e30f; int bi = Ss;
        for (int i = t; i < Ss; i += 256) {
            float vv = s[i];
            if (vv > bv || (vv == bv && i < bi)) { bv = vv; bi = i; }
        }
        rv[t] = bv; ri[t] = bi;
        __syncthreads();
        for (int off = 128; off > 0; off >>= 1) {
            if (t < off) {
                float ov = rv[t + off]; int oi = ri[t + off];
                if (ov > rv[t] || (ov == rv[t] && oi < ri[t])) { rv[t] = ov; ri[t] = oi; }
            }
            __syncthreads();
        }
        if (t == 0) { g_idx[b * KTOK + sel] = ri[0]; s[ri[0]] = -1e30f; }
        __syncthreads();
    }
}

// ---------------------------------------------------------------------------
// Kernel 4: gather selected tokens into d_out; append indices as float
// ---------------------------------------------------------------------------
__global__ void __launch_bounds__(192)
gather_kernel(const float* __restrict__ features, float* __restrict__ out,
              long long out_size) {
    const int blk = blockIdx.x;          // b*40 + k
    const int b   = blk / KTOK;
    const int tok = g_idx[blk];
    const int t   = threadIdx.x;         // 192 threads, 1 float4 each

    long long base = (long long)blk * Dd;
    if (base + (t + 1) * 4 <= out_size) {
        const float4* src = (const float4*)(features + ((size_t)b * Ss + tok) * Dd);
        float4* dst = (float4*)(out + base);
        dst[t] = src[t];
    }
    if (t == 0) {
        long long pos = (long long)Bb * KTOK * Dd + blk;
        if (pos < out_size) out[pos] = (float)tok;
    }
}

__global__ void fill_zero_kernel(float* __restrict__ out, long long start, long long end) {
    long long i = start + blockIdx.x * (long long)blockDim.x + threadIdx.x;
    if (i < end) out[i] = 0.f;
}

// ---------------------------------------------------------------------------
extern "C" void kernel_launch(void* const* d_in, const int* in_sizes, int n_in,
                              void* d_out, int out_size) {
    const float* features = (const float*)d_in[0];
    const float* W1       = (const float*)d_in[1];
    const float* b1       = (const float*)d_in[2];
    const float* ln_gamma = (const float*)d_in[3];
    const float* ln_beta  = (const float*)d_in[4];
    const float* W2       = (const float*)d_in[5];
    const float* b2       = (const float*)d_in[6];
    float* out = (float*)d_out;

    // 1) h = features @ W1 + b1
    dim3 ggrid(Hh / BN, Mtot / BM);   // (3, 512)
    gemm_kernel<<<ggrid, 256>>>(features, W1, b1);

    // 2) LN + GELU + W2 + sigmoid -> scores
    score_kernel<<<Mtot / 8, 256>>>(ln_gamma, ln_beta, W2, b2);

    // 3) top-40 per batch
    topk_kernel<<<Bb, 256>>>();

    // 4) gather + indices
    gather_kernel<<<Bb * KTOK, 192>>>(features, out, (long long)out_size);

    // zero any tail beyond (tokens + indices) so no poison survives
    long long written = (long long)Bb * KTOK * Dd + (long long)Bb * KTOK;
    if ((long long)out_size > written) {
        long long n = (long long)out_size - written;
        int blocks = (int)((n + 255) / 256);
        fill_zero_kernel<<<blocks, 256>>>(out, written, (long long)out_size);
    }
}

// round 4
// speedup vs baseline: 2.9290x; 2.5609x over previous
#include <cuda_runtime.h>
#include <cuda_bf16.h>
#include <math.h>
#include <stdint.h>

// Problem shape (fixed)
#define Bb   16
#define Ss   4096
#define Dd   768
#define Hh   384
#define KTOK 40
#define KSEL 48
#define Mtot (Bb * Ss)   // 65536

// ---------------------------------------------------------------------------
// Device scratch
// ---------------------------------------------------------------------------
__device__ __nv_bfloat16 g_Wt[(size_t)Hh * Dd];   // W1^T bf16 [n][k]
__device__ float         g_scores[Mtot];
__device__ int           g_cand[Bb * KSEL];
__device__ float         g_exact[Bb * KSEL];
__device__ int           g_idx[Bb * KTOK];

// ---------------------------------------------------------------------------
// Kernel 0: convert + transpose W1 [768,384] f32 -> g_Wt [384][768] bf16
// ---------------------------------------------------------------------------
__global__ void convw_kernel(const float* __restrict__ W1) {
    int i = blockIdx.x * blockDim.x + threadIdx.x;
    if (i >= Dd * Hh) return;
    int k = i / Hh, n = i % Hh;
    g_Wt[(size_t)n * Dd + k] = __float2bfloat16_rn(W1[i]);
}

// ---------------------------------------------------------------------------
// Fused GEMM + score kernel.
//   CTA: 64 tokens x full H=384, K=768 in 12 chunks of 64.
//   256 threads = 8 warps as 2(M) x 4(N); warp tile 32x96.
//   mma.sync m16n8k16 bf16 (baseline PTX, runs on sm_103 tensor pipe).
//   Epilogue: LN + exact GELU + dot(W2) + sigmoid -> g_scores (no g_h!).
// ---------------------------------------------------------------------------
#define GBM 64
#define GBK 64
#define NCH (Dd / GBK)          // 12
#define APITCH 144              // (64+8) bf16 * 2B, conflict-free rows
#define ABUF_SZ (GBM * APITCH)          // 9216 B
#define BBUF_SZ (Hh * APITCH)           // 55296 B
#define OFF_B (2 * ABUF_SZ)             // 18432
#define SMEM_FUSED (2 * ABUF_SZ + 2 * BBUF_SZ)   // 129024 B
#define EPITCH 388              // epilogue f32 pitch

__device__ __forceinline__ void cp16(uint32_t saddr, const void* gptr) {
    asm volatile("cp.async.cg.shared.global [%0], [%1], 16;"
                 :: "r"(saddr), "l"(gptr));
}
__device__ __forceinline__ void mma_bf16(float* c, const uint32_t* a,
                                         uint32_t b0, uint32_t b1) {
    asm volatile(
        "mma.sync.aligned.m16n8k16.row.col.f32.bf16.bf16.f32 "
        "{%0,%1,%2,%3}, {%4,%5,%6,%7}, {%8,%9}, {%0,%1,%2,%3};"
        : "+f"(c[0]), "+f"(c[1]), "+f"(c[2]), "+f"(c[3])
        : "r"(a[0]), "r"(a[1]), "r"(a[2]), "r"(a[3]), "r"(b0), "r"(b1));
}
__device__ __forceinline__ uint32_t smem_u32(const void* p) {
    uint32_t a;
    asm("{ .reg .u64 t; cvta.to.shared.u64 t, %1; cvt.u32.u64 %0, t; }"
        : "=r"(a) : "l"(p));
    return a;
}
__device__ __forceinline__ uint32_t packbf(float x, float y) {
    __nv_bfloat16 hx = __float2bfloat16_rn(x);
    __nv_bfloat16 hy = __float2bfloat16_rn(y);
    return (uint32_t)__bfloat16_as_ushort(hx)
         | ((uint32_t)__bfloat16_as_ushort(hy) << 16);
}

__global__ void __launch_bounds__(256)
gemmscore_kernel(const float* __restrict__ A,  const float* __restrict__ b1,
                 const float* __restrict__ gamma, const float* __restrict__ beta,
                 const float* __restrict__ W2, const float* __restrict__ b2) {
    extern __shared__ char smem[];
    const uint32_t sb = smem_u32(smem);
    const int tid  = threadIdx.x;
    const int lane = tid & 31, wid = tid >> 5;
    const int wm = wid >> 2, wn = wid & 3;       // 2 x 4 warp grid
    const int m0 = blockIdx.x * GBM;

    const int qt = lane & 3, rt = lane >> 2;     // fragment lane decomposition

    float acc[2][12][4];
    #pragma unroll
    for (int mi = 0; mi < 2; mi++)
        #pragma unroll
        for (int ni = 0; ni < 12; ni++)
            #pragma unroll
            for (int j = 0; j < 4; j++) acc[mi][ni][j] = 0.f;

    // cp.async lane mapping for B: 3072 uint4, 12 per thread
    // A LDG mapping: 1024 float4, 4 per thread
    const __nv_bfloat16* Wt = g_Wt;

    // ---- preload chunk 0 ----
    {   // B chunk 0 -> buf0
        #pragma unroll
        for (int i = 0; i < 12; i++) {
            int f = tid + i * 256;
            int n = f >> 3, j = f & 7;
            cp16(sb + OFF_B + n * APITCH + j * 16,
                 Wt + (size_t)n * Dd + 0 * GBK + j * 8);
        }
        asm volatile("cp.async.commit_group;");
    }
    float4 av[4];
    #pragma unroll
    for (int i = 0; i < 4; i++) {
        int f = tid + i * 256;
        int r = f >> 4, q = f & 15;
        av[i] = *(const float4*)(A + (size_t)(m0 + r) * Dd + q * 4);
    }

    for (int c = 0; c < NCH; c++) {
        const int s = c & 1;
        const char* pa = smem + s * ABUF_SZ;
        const char* pb = smem + OFF_B + s * BBUF_SZ;

        // issue B for chunk c+1
        if (c + 1 < NCH) {
            const int s1 = (c + 1) & 1;
            #pragma unroll
            for (int i = 0; i < 12; i++) {
                int f = tid + i * 256;
                int n = f >> 3, j = f & 7;
                cp16(sb + OFF_B + s1 * BBUF_SZ + n * APITCH + j * 16,
                     Wt + (size_t)n * Dd + (c + 1) * GBK + j * 8);
            }
            asm volatile("cp.async.commit_group;");
        }

        // STS A chunk c (convert fp32->bf16)
        #pragma unroll
        for (int i = 0; i < 4; i++) {
            int f = tid + i * 256;
            int r = f >> 4, q = f & 15;
            uint2 p;
            p.x = packbf(av[i].x, av[i].y);
            p.y = packbf(av[i].z, av[i].w);
            *(uint2*)((char*)smem + s * ABUF_SZ + r * APITCH + q * 8) = p;
        }

        // wait for B chunk c (keep at most the newest group in flight)
        if (c + 1 < NCH) asm volatile("cp.async.wait_group 1;");
        else             asm volatile("cp.async.wait_group 0;");
        __syncthreads();

        // prefetch A chunk c+1 (overlaps compute)
        if (c + 1 < NCH) {
            #pragma unroll
            for (int i = 0; i < 4; i++) {
                int f = tid + i * 256;
                int r = f >> 4, q = f & 15;
                av[i] = *(const float4*)(A + (size_t)(m0 + r) * Dd
                                           + (c + 1) * GBK + q * 4);
            }
        }

        // ---- compute chunk c: 4 k16 steps ----
        #pragma unroll
        for (int ks = 0; ks < 4; ks++) {
            const int kb = ks * 16;
            uint32_t afr[2][4];
            #pragma unroll
            for (int mi = 0; mi < 2; mi++) {
                int r0 = wm * 32 + mi * 16 + rt;
                afr[mi][0] = *(const uint32_t*)(pa + r0 * APITCH + (kb + 2 * qt) * 2);
                afr[mi][1] = *(const uint32_t*)(pa + (r0 + 8) * APITCH + (kb + 2 * qt) * 2);
                afr[mi][2] = *(const uint32_t*)(pa + r0 * APITCH + (kb + 2 * qt + 8) * 2);
                afr[mi][3] = *(const uint32_t*)(pa + (r0 + 8) * APITCH + (kb + 2 * qt + 8) * 2);
            }
            #pragma unroll
            for (int ni = 0; ni < 12; ni++) {
                int n = wn * 96 + ni * 8 + rt;
                uint32_t b0 = *(const uint32_t*)(pb + n * APITCH + (kb + 2 * qt) * 2);
                uint32_t b1 = *(const uint32_t*)(pb + n * APITCH + (kb + 2 * qt + 8) * 2);
                mma_bf16(acc[0][ni], afr[0], b0, b1);
                mma_bf16(acc[1][ni], afr[1], b0, b1);
            }
        }
        __syncthreads();
    }

    // ---- epilogue: acc -> SMEM (f32, pitch 388), then LN+GELU+W2+sigmoid ----
    float* eb = (float*)smem;
    #pragma unroll
    for (int mi = 0; mi < 2; mi++) {
        #pragma unroll
        for (int ni = 0; ni < 12; ni++) {
            int r0  = wm * 32 + mi * 16 + rt;
            int col = wn * 96 + ni * 8 + 2 * qt;
            *(float2*)&eb[r0 * EPITCH + col]       = make_float2(acc[mi][ni][0], acc[mi][ni][1]);
            *(float2*)&eb[(r0 + 8) * EPITCH + col] = make_float2(acc[mi][ni][2], acc[mi][ni][3]);
        }
    }
    __syncthreads();

    // per-warp: rows [wid*8, wid*8+8)
    float gm[12], bt[12], w2r[12], b1r[12];
    #pragma unroll
    for (int i = 0; i < 12; i++) {
        int j = lane + 32 * i;
        gm[i]  = gamma[j];
        bt[i]  = beta[j];
        w2r[i] = W2[j];
        b1r[i] = b1[j];
    }
    const float b2v = b2[0];
    for (int rr = 0; rr < 8; rr++) {
        const int row = wid * 8 + rr;
        float x[12];
        float sum = 0.f;
        #pragma unroll
        for (int i = 0; i < 12; i++) {
            x[i] = eb[row * EPITCH + lane + 32 * i] + b1r[i];
            sum += x[i];
        }
        #pragma unroll
        for (int o = 16; o > 0; o >>= 1) sum += __shfl_xor_sync(0xffffffffu, sum, o);
        const float mu = sum * (1.0f / Hh);
        float sq = 0.f;
        #pragma unroll
        for (int i = 0; i < 12; i++) { float d = x[i] - mu; sq += d * d; }
        #pragma unroll
        for (int o = 16; o > 0; o >>= 1) sq += __shfl_xor_sync(0xffffffffu, sq, o);
        const float rstd = 1.0f / sqrtf(sq * (1.0f / Hh) + 1e-5f);
        float dot = 0.f;
        #pragma unroll
        for (int i = 0; i < 12; i++) {
            float xn = (x[i] - mu) * rstd * gm[i] + bt[i];
            float ge = 0.5f * xn * (1.0f + erff(xn * 0.70710678118654752f));
            dot += ge * w2r[i];
        }
        #pragma unroll
        for (int o = 16; o > 0; o >>= 1) dot += __shfl_xor_sync(0xffffffffu, dot, o);
        if (lane == 0)
            g_scores[m0 + row] = 1.0f / (1.0f + expf(-(dot + b2v)));
    }
}

// ---------------------------------------------------------------------------
// top-48 candidates per batch on approx scores (ties -> lower index)
// ---------------------------------------------------------------------------
__global__ void __launch_bounds__(256)
topk_kernel() {
    __shared__ float s[Ss];
    __shared__ float rv[256];
    __shared__ int   ri[256];
    const int b = blockIdx.x;
    const int t = threadIdx.x;
    for (int i = t; i < Ss; i += 256) s[i] = g_scores[b * Ss + i];
    __syncthreads();
    for (int sel = 0; sel < KSEL; sel++) {
        float bv = -1e30f; int bi = Ss;
        for (int i = t; i < Ss; i += 256) {
            float vv = s[i];
            if (vv > bv || (vv == bv && i < bi)) { bv = vv; bi = i; }
        }
        rv[t] = bv; ri[t] = bi;
        __syncthreads();
        for (int off = 128; off > 0; off >>= 1) {
            if (t < off) {
                float ov = rv[t + off]; int oi = ri[t + off];
                if (ov > rv[t] || (ov == rv[t] && oi < ri[t])) { rv[t] = ov; ri[t] = oi; }
            }
            __syncthreads();
        }
        if (t == 0) { g_cand[b * KSEL + sel] = ri[0]; s[ri[0]] = -1e30f; }
        __syncthreads();
    }
}

// ---------------------------------------------------------------------------
// exact fp32 rescore of the 48 candidates per batch
// ---------------------------------------------------------------------------
__device__ __forceinline__ float block_reduce384(float v, float* red,
                                                 int tid, int wid, int lane) {
    #pragma unroll
    for (int o = 16; o > 0; o >>= 1) v += __shfl_xor_sync(0xffffffffu, v, o);
    __syncthreads();
    if (lane == 0) red[wid] = v;
    __syncthreads();
    if (tid == 0) {
        float tot = 0.f;
        #pragma unroll
        for (int i = 0; i < 12; i++) tot += red[i];
        red[12] = tot;
    }
    __syncthreads();
    return red[12];
}

__global__ void __launch_bounds__(384)
rescore_kernel(const float* __restrict__ features, const float* __restrict__ W1,
               const float* __restrict__ b1, const float* __restrict__ gamma,
               const float* __restrict__ beta, const float* __restrict__ W2,
               const float* __restrict__ b2) {
    __shared__ float feat[12][Dd];
    __shared__ float red[16];
    const int batch = blockIdx.x >> 2;
    const int grp   = blockIdx.x & 3;
    const int t = threadIdx.x, wid = t >> 5, lane = t & 31;

    for (int j = 0; j < 12; j++) {
        int tok = g_cand[batch * KSEL + grp * 12 + j];
        const float* src = features + ((size_t)batch * Ss + tok) * Dd;
        for (int k = t; k < Dd; k += 384) feat[j][k] = src[k];
    }
    __syncthreads();

    float acc[12];
    #pragma unroll
    for (int j = 0; j < 12; j++) acc[j] = 0.f;
    for (int k = 0; k < Dd; k++) {
        float w = W1[(size_t)k * Hh + t];
        #pragma unroll
        for (int j = 0; j < 12; j++) acc[j] += feat[j][k] * w;
    }

    const float bv = b1[t], gmv = gamma[t], btv = beta[t], w2 = W2[t];
    const float b2v = b2[0];
    for (int j = 0; j < 12; j++) {
        float x  = acc[j] + bv;
        float mu = block_reduce384(x, red, t, wid, lane) * (1.0f / Hh);
        float d  = x - mu;
        float var = block_reduce384(d * d, red, t, wid, lane) * (1.0f / Hh);
        float rstd = 1.0f / sqrtf(var + 1e-5f);
        float xn = d * rstd * gmv + btv;
        float ge = 0.5f * xn * (1.0f + erff(xn * 0.70710678118654752f));
        float s  = block_reduce384(ge * w2, red, t, wid, lane);
        if (t == 0)
            g_exact[batch * KSEL + grp * 12 + j] = 1.0f / (1.0f + expf(-(s + b2v)));
    }
}

// ---------------------------------------------------------------------------
// final exact top-40 from 48 candidates (ties -> lower index)
// ---------------------------------------------------------------------------
__global__ void select_kernel() {
    int b = threadIdx.x;
    if (b >= Bb) return;
    float sc[KSEL]; int id[KSEL];
    for (int i = 0; i < KSEL; i++) {
        sc[i] = g_exact[b * KSEL + i];
        id[i] = g_cand [b * KSEL + i];
    }
    for (int sel = 0; sel < KTOK; sel++) {
        int best = sel;
        for (int i = sel + 1; i < KSEL; i++)
            if (sc[i] > sc[best] || (sc[i] == sc[best] && id[i] < id[best])) best = i;
        float tv = sc[sel]; sc[sel] = sc[best]; sc[best] = tv;
        int   ti = id[sel]; id[sel] = id[best]; id[best] = ti;
        g_idx[b * KTOK + sel] = id[sel];
    }
}

// ---------------------------------------------------------------------------
// gather tokens + indices into d_out
// ---------------------------------------------------------------------------
__global__ void __launch_bounds__(192)
gather_kernel(const float* __restrict__ features, float* __restrict__ out,
              long long out_size) {
    const int blk = blockIdx.x;
    const int b   = blk / KTOK;
    const int tok = g_idx[blk];
    const int t   = threadIdx.x;
    long long base = (long long)blk * Dd;
    if (base + (t + 1) * 4 <= out_size) {
        const float4* src = (const float4*)(features + ((size_t)b * Ss + tok) * Dd);
        ((float4*)(out + base))[t] = src[t];
    }
    if (t == 0) {
        long long pos = (long long)Bb * KTOK * Dd + blk;
        if (pos < out_size) out[pos] = (float)tok;
    }
}

__global__ void fill_zero_kernel(float* __restrict__ out, long long start, long long end) {
    long long i = start + blockIdx.x * (long long)blockDim.x + threadIdx.x;
    if (i < end) out[i] = 0.f;
}

// ---------------------------------------------------------------------------
extern "C" void kernel_launch(void* const* d_in, const int* in_sizes, int n_in,
                              void* d_out, int out_size) {
    const float* features = (const float*)d_in[0];
    const float* W1       = (const float*)d_in[1];
    const float* b1       = (const float*)d_in[2];
    const float* ln_gamma = (const float*)d_in[3];
    const float* ln_beta  = (const float*)d_in[4];
    const float* W2       = (const float*)d_in[5];
    const float* b2       = (const float*)d_in[6];
    float* out = (float*)d_out;

    cudaFuncSetAttribute(gemmscore_kernel,
                         cudaFuncAttributeMaxDynamicSharedMemorySize, SMEM_FUSED);

    convw_kernel<<<(Dd * Hh + 255) / 256, 256>>>(W1);

    gemmscore_kernel<<<Mtot / GBM, 256, SMEM_FUSED>>>(
        features, b1, ln_gamma, ln_beta, W2, b2);

    topk_kernel<<<Bb, 256>>>();
    rescore_kernel<<<Bb * 4, 384>>>(features, W1, b1, ln_gamma, ln_beta, W2, b2);
    select_kernel<<<1, Bb>>>();
    gather_kernel<<<Bb * KTOK, 192>>>(features, out, (long long)out_size);

    long long written = (long long)Bb * KTOK * Dd + (long long)Bb * KTOK;
    if ((long long)out_size > written) {
        long long n = (long long)out_size - written;
        int blocks = (int)((n + 255) / 256);
        fill_zero_kernel<<<blocks, 256>>>(out, written, (long long)out_size);
    }
}

// round 5
// speedup vs baseline: 3.6487x; 1.2457x over previous
#include <cuda_runtime.h>
#include <cuda_bf16.h>
#include <math.h>
#include <stdint.h>

// Problem shape (fixed)
#define Bb   16
#define Ss   4096
#define Dd   768
#define Hh   384
#define KTOK 40
#define KSEL 48
#define Mtot (Bb * Ss)   // 65536

// ---------------------------------------------------------------------------
// Device scratch
// ---------------------------------------------------------------------------
__device__ __nv_bfloat16 g_Wt [(size_t)Hh * Dd];  // W1^T bf16 [n][k]
__device__ float         g_Wtf[(size_t)Hh * Dd];  // W1^T f32  [n][k] (exact)
__device__ float         g_scores[Mtot];
__device__ float         g_hex[(size_t)Bb * KSEL * Hh];  // exact h for candidates
__device__ int           g_cand[Bb * KSEL];
__device__ float         g_exact[Bb * KSEL];
__device__ int           g_idx[Bb * KTOK];

// ---------------------------------------------------------------------------
// helpers
// ---------------------------------------------------------------------------
__device__ __forceinline__ uint32_t smem_u32(const void* p) {
    uint32_t a;
    asm("{ .reg .u64 t; cvta.to.shared.u64 t, %1; cvt.u32.u64 %0, t; }"
        : "=r"(a) : "l"(p));
    return a;
}
__device__ __forceinline__ void cp16(uint32_t saddr, const void* gptr) {
    asm volatile("cp.async.cg.shared.global [%0], [%1], 16;"
                 :: "r"(saddr), "l"(gptr));
}
__device__ __forceinline__ void mma_bf16(float* c, const uint32_t* a,
                                         uint32_t b0, uint32_t b1) {
    asm volatile(
        "mma.sync.aligned.m16n8k16.row.col.f32.bf16.bf16.f32 "
        "{%0,%1,%2,%3}, {%4,%5,%6,%7}, {%8,%9}, {%0,%1,%2,%3};"
        : "+f"(c[0]), "+f"(c[1]), "+f"(c[2]), "+f"(c[3])
        : "r"(a[0]), "r"(a[1]), "r"(a[2]), "r"(a[3]), "r"(b0), "r"(b1));
}
// pack two f32 -> bf16x2 (low = x, high = y)
__device__ __forceinline__ uint32_t cvtpack(float2 v) {
    uint32_t r;
    asm("cvt.rn.bf16x2.f32 %0, %1, %2;" : "=r"(r) : "f"(v.y), "f"(v.x));
    return r;
}

// ---------------------------------------------------------------------------
// Kernel 0: convert + transpose W1 [768,384] f32 -> g_Wt (bf16), g_Wtf (f32)
// ---------------------------------------------------------------------------
__global__ void convw_kernel(const float* __restrict__ W1) {
    int i = blockIdx.x * blockDim.x + threadIdx.x;
    if (i >= Dd * Hh) return;
    int k = i / Hh, n = i % Hh;
    float v = W1[i];
    g_Wt [(size_t)n * Dd + k] = __float2bfloat16_rn(v);
    g_Wtf[(size_t)n * Dd + k] = v;
}

// ---------------------------------------------------------------------------
// Fused GEMM + score kernel.  CTA: 64 tokens x H=384, K in 24 chunks of 32.
//   256 threads = 8 warps (2M x 4N), warp tile 32x96, mma m16n8k16 bf16.
//   A kept fp32 in smem (cp.async), converted at fragment load.
//   2 CTAs/SM (smem 80KB, regs capped 128).  Epilogue: LN+GELU+W2+sigmoid.
// ---------------------------------------------------------------------------
#define GBM 64
#define GBK 32
#define NCH (Dd / GBK)          // 24
#define APITCH 160              // bytes: 32 f32 + 32B pad
#define BPITCH 80               // bytes: 32 bf16 + 16B pad
#define ABUF (GBM * APITCH)             // 10240
#define BBUF (Hh * BPITCH)              // 30720
#define OFF_B (2 * ABUF)                // 20480
#define SMEM_FUSED (2 * ABUF + 2 * BBUF)  // 81920
#define EPITCH 388

__global__ void __launch_bounds__(256, 2)
gemmscore_kernel(const float* __restrict__ A,  const float* __restrict__ b1,
                 const float* __restrict__ gamma, const float* __restrict__ beta,
                 const float* __restrict__ W2, const float* __restrict__ b2) {
    extern __shared__ char smem[];
    const uint32_t sb = smem_u32(smem);
    const int tid  = threadIdx.x;
    const int lane = tid & 31, wid = tid >> 5;
    const int wm = wid >> 2, wn = wid & 3;       // 2 x 4 warp grid
    const int m0 = blockIdx.x * GBM;
    const int qt = lane & 3, rt = lane >> 2;

    float acc[2][12][4];
    #pragma unroll
    for (int mi = 0; mi < 2; mi++)
        #pragma unroll
        for (int ni = 0; ni < 12; ni++)
            #pragma unroll
            for (int j = 0; j < 4; j++) acc[mi][ni][j] = 0.f;

    // lane mappings for cp.async
    const int ar = tid >> 3, aj = tid & 7;           // A: 512 16B-chunks, 2/thread
    const int ar2 = (tid + 256) >> 3, aj2 = (tid + 256) & 7;
    // B: 1536 16B-chunks, 6/thread

    // ---- preload chunk 0 ----
    cp16(sb + ar  * APITCH + aj  * 16, A + (size_t)(m0 + ar)  * Dd + aj  * 4);
    cp16(sb + ar2 * APITCH + aj2 * 16, A + (size_t)(m0 + ar2) * Dd + aj2 * 4);
    #pragma unroll
    for (int i = 0; i < 6; i++) {
        int f = tid + i * 256;
        int n = f >> 2, j = f & 3;
        cp16(sb + OFF_B + n * BPITCH + j * 16, g_Wt + (size_t)n * Dd + j * 8);
    }
    asm volatile("cp.async.commit_group;");

    for (int c = 0; c < NCH; c++) {
        const int s = c & 1;
        const char* pa = smem + s * ABUF;
        const char* pb = smem + OFF_B + s * BBUF;

        if (c + 1 < NCH) {
            const int s1 = (c + 1) & 1;
            const int ko = (c + 1) * GBK;
            cp16(sb + s1 * ABUF + ar  * APITCH + aj  * 16,
                 A + (size_t)(m0 + ar)  * Dd + ko + aj  * 4);
            cp16(sb + s1 * ABUF + ar2 * APITCH + aj2 * 16,
                 A + (size_t)(m0 + ar2) * Dd + ko + aj2 * 4);
            #pragma unroll
            for (int i = 0; i < 6; i++) {
                int f = tid + i * 256;
                int n = f >> 2, j = f & 3;
                cp16(sb + OFF_B + s1 * BBUF + n * BPITCH + j * 16,
                     g_Wt + (size_t)n * Dd + ko + j * 8);
            }
            asm volatile("cp.async.commit_group;");
            asm volatile("cp.async.wait_group 1;");
        } else {
            asm volatile("cp.async.wait_group 0;");
        }
        __syncthreads();

        #pragma unroll
        for (int ks = 0; ks < 2; ks++) {
            const int kb = ks * 16;
            uint32_t afr[2][4];
            #pragma unroll
            for (int mi = 0; mi < 2; mi++) {
                int r0 = wm * 32 + mi * 16 + rt;
                float2 a0 = *(const float2*)(pa + r0 * APITCH + (kb + 2 * qt) * 4);
                float2 a1 = *(const float2*)(pa + (r0 + 8) * APITCH + (kb + 2 * qt) * 4);
                float2 a2 = *(const float2*)(pa + r0 * APITCH + (kb + 2 * qt + 8) * 4);
                float2 a3 = *(const float2*)(pa + (r0 + 8) * APITCH + (kb + 2 * qt + 8) * 4);
                afr[mi][0] = cvtpack(a0);
                afr[mi][1] = cvtpack(a1);
                afr[mi][2] = cvtpack(a2);
                afr[mi][3] = cvtpack(a3);
            }
            #pragma unroll
            for (int ni = 0; ni < 12; ni++) {
                int n = wn * 96 + ni * 8 + rt;
                uint32_t b0 = *(const uint32_t*)(pb + n * BPITCH + (kb + 2 * qt) * 2);
                uint32_t b1v = *(const uint32_t*)(pb + n * BPITCH + (kb + 2 * qt + 8) * 2);
                mma_bf16(acc[0][ni], afr[0], b0, b1v);
                mma_bf16(acc[1][ni], afr[1], b0, b1v);
            }
        }
        __syncthreads();
    }

    // ---- epilogue: two passes of 32 rows (eb = 32 x 388 f32 <= smem) ----
    float* eb = (float*)smem;
    float gm[12], bt[12], w2r[12], b1r[12];
    #pragma unroll
    for (int i = 0; i < 12; i++) {
        int j = lane + 32 * i;
        gm[i]  = gamma[j];
        bt[i]  = beta[j];
        w2r[i] = W2[j];
        b1r[i] = b1[j];
    }
    const float b2v = b2[0];

    #pragma unroll
    for (int p = 0; p < 2; p++) {
        if (wm == p) {
            #pragma unroll
            for (int mi = 0; mi < 2; mi++) {
                #pragma unroll
                for (int ni = 0; ni < 12; ni++) {
                    int rl  = mi * 16 + rt;
                    int col = wn * 96 + ni * 8 + 2 * qt;
                    *(float2*)&eb[rl * EPITCH + col] =
                        make_float2(acc[mi][ni][0], acc[mi][ni][1]);
                    *(float2*)&eb[(rl + 8) * EPITCH + col] =
                        make_float2(acc[mi][ni][2], acc[mi][ni][3]);
                }
            }
        }
        __syncthreads();
        #pragma unroll
        for (int rr = 0; rr < 4; rr++) {
            const int rowl = wid * 4 + rr;
            float x[12];
            float sum = 0.f;
            #pragma unroll
            for (int i = 0; i < 12; i++) {
                x[i] = eb[rowl * EPITCH + lane + 32 * i] + b1r[i];
                sum += x[i];
            }
            #pragma unroll
            for (int o = 16; o > 0; o >>= 1) sum += __shfl_xor_sync(0xffffffffu, sum, o);
            const float mu = sum * (1.0f / Hh);
            float sq = 0.f;
            #pragma unroll
            for (int i = 0; i < 12; i++) { float d = x[i] - mu; sq += d * d; }
            #pragma unroll
            for (int o = 16; o > 0; o >>= 1) sq += __shfl_xor_sync(0xffffffffu, sq, o);
            const float rstd = 1.0f / sqrtf(sq * (1.0f / Hh) + 1e-5f);
            float dot = 0.f;
            #pragma unroll
            for (int i = 0; i < 12; i++) {
                float xn = (x[i] - mu) * rstd * gm[i] + bt[i];
                float ge = 0.5f * xn * (1.0f + erff(xn * 0.70710678118654752f));
                dot += ge * w2r[i];
            }
            #pragma unroll
            for (int o = 16; o > 0; o >>= 1) dot += __shfl_xor_sync(0xffffffffu, dot, o);
            if (lane == 0)
                g_scores[m0 + p * 32 + rowl] = 1.0f / (1.0f + expf(-(dot + b2v)));
        }
        __syncthreads();
    }
}

// ---------------------------------------------------------------------------
// top-48 candidates per batch, u64-key warp-shfl argmax (ties -> lower index)
// ---------------------------------------------------------------------------
__device__ __forceinline__ unsigned long long score_key(float f, int i) {
    uint32_t b = __float_as_uint(f);
    uint32_t flip = (b & 0x80000000u) ? ~b : (b | 0x80000000u);
    return ((unsigned long long)flip << 32) | (uint32_t)(Ss - 1 - i);
}

__global__ void __launch_bounds__(256)
topk_kernel() {
    __shared__ float s[Ss];
    __shared__ unsigned long long wred[8];
    const int b = blockIdx.x;
    const int t = threadIdx.x;
    const int lane = t & 31, wid = t >> 5;

    for (int i = t; i < Ss; i += 256) s[i] = g_scores[b * Ss + i];
    __syncthreads();

    for (int sel = 0; sel < KSEL; sel++) {
        unsigned long long best = 0ull;
        #pragma unroll
        for (int u = 0; u < Ss / 256; u++) {
            int i = t + u * 256;
            unsigned long long k = score_key(s[i], i);
            if (k > best) best = k;
        }
        #pragma unroll
        for (int o = 16; o > 0; o >>= 1) {
            unsigned long long ok = __shfl_xor_sync(0xffffffffu, best, o);
            if (ok > best) best = ok;
        }
        if (lane == 0) wred[wid] = best;
        __syncthreads();
        if (t < 8) {
            unsigned long long v = wred[t];
            #pragma unroll
            for (int o = 4; o > 0; o >>= 1) {
                unsigned long long ov = __shfl_xor_sync(0xffu, v, o, 8);
                if (ov > v) v = ov;
            }
            if (t == 0) {
                int idx = Ss - 1 - (int)(v & 0xFFFFFFFFu);
                g_cand[b * KSEL + sel] = idx;
                s[idx] = -1.0f;
            }
        }
        __syncthreads();
    }
}

// ---------------------------------------------------------------------------
// rescore GEMM: exact fp32 h for 768 candidates.
//   256 blocks = (batch 16) x (token-group 4) x (col-quarter 4).
//   384 threads: 12 warps = (col-32-group 3) x (k-quarter 4).
// ---------------------------------------------------------------------------
__global__ void __launch_bounds__(384)
rescore_gemm_kernel(const float* __restrict__ features, const float* __restrict__ b1) {
    extern __shared__ char rsm[];
    float* feat = (float*)rsm;                 // 12 x 768
    float* part = feat + 12 * Dd;              // 4 x 12 x 96

    const int blk = blockIdx.x;
    const int b   = blk >> 4;
    const int grp = (blk >> 2) & 3;
    const int cq  = blk & 3;
    const int t = threadIdx.x, lane = t & 31, wid = t >> 5;
    const int kq = wid & 3, cg = wid >> 2;     // k-quarter, col-32-group
    const int col_local = cg * 32 + lane;      // 0..95
    const int col = cq * 96 + col_local;

    const int cbase = b * KSEL + grp * 12;
    for (int j = 0; j < 12; j++) {
        int tok = g_cand[cbase + j];
        const float* src = features + ((size_t)b * Ss + tok) * Dd;
        for (int k = t; k < Dd; k += 384) feat[j * Dd + k] = src[k];
    }
    __syncthreads();

    float acc[12];
    #pragma unroll
    for (int j = 0; j < 12; j++) acc[j] = 0.f;
    const float4* wp = (const float4*)(g_Wtf + (size_t)col * Dd) + kq * 48;
    #pragma unroll 4
    for (int it = 0; it < 48; it++) {
        float4 w = wp[it];
        #pragma unroll
        for (int j = 0; j < 12; j++) {
            float4 f = *((const float4*)(feat + j * Dd + kq * 192) + it);
            acc[j] = fmaf(f.x, w.x,
                     fmaf(f.y, w.y,
                     fmaf(f.z, w.z,
                     fmaf(f.w, w.w, acc[j]))));
        }
    }
    #pragma unroll
    for (int j = 0; j < 12; j++)
        part[(kq * 12 + j) * 96 + col_local] = acc[j];
    __syncthreads();

    for (int idx = t; idx < 12 * 96; idx += 384) {
        int j = idx / 96, c = idx % 96;
        float h = part[(0 * 12 + j) * 96 + c] + part[(1 * 12 + j) * 96 + c]
                + part[(2 * 12 + j) * 96 + c] + part[(3 * 12 + j) * 96 + c]
                + b1[cq * 96 + c];
        g_hex[(size_t)(cbase + j) * Hh + cq * 96 + c] = h;
    }
}
#define SMEM_RGEMM ((12 * Dd + 4 * 12 * 96) * 4)   // 55296 B

// ---------------------------------------------------------------------------
// rescore LN: warp per candidate token -> exact score
// ---------------------------------------------------------------------------
__global__ void __launch_bounds__(256)
rescore_ln_kernel(const float* __restrict__ gamma, const float* __restrict__ beta,
                  const float* __restrict__ W2, const float* __restrict__ b2) {
    const int lane = threadIdx.x & 31, wid = threadIdx.x >> 5;
    const int cand = blockIdx.x * 8 + wid;     // 0..767
    const float* row = g_hex + (size_t)cand * Hh;

    float x[12];
    float sum = 0.f;
    #pragma unroll
    for (int i = 0; i < 12; i++) { x[i] = row[lane + 32 * i]; sum += x[i]; }
    #pragma unroll
    for (int o = 16; o > 0; o >>= 1) sum += __shfl_xor_sync(0xffffffffu, sum, o);
    const float mu = sum * (1.0f / Hh);
    float sq = 0.f;
    #pragma unroll
    for (int i = 0; i < 12; i++) { float d = x[i] - mu; sq += d * d; }
    #pragma unroll
    for (int o = 16; o > 0; o >>= 1) sq += __shfl_xor_sync(0xffffffffu, sq, o);
    const float rstd = 1.0f / sqrtf(sq * (1.0f / Hh) + 1e-5f);
    float dot = 0.f;
    #pragma unroll
    for (int i = 0; i < 12; i++) {
        float xn = (x[i] - mu) * rstd * gamma[lane + 32 * i] + beta[lane + 32 * i];
        float ge = 0.5f * xn * (1.0f + erff(xn * 0.70710678118654752f));
        dot += ge * W2[lane + 32 * i];
    }
    #pragma unroll
    for (int o = 16; o > 0; o >>= 1) dot += __shfl_xor_sync(0xffffffffu, dot, o);
    if (lane == 0)
        g_exact[cand] = 1.0f / (1.0f + expf(-(dot + b2[0])));
}

// ---------------------------------------------------------------------------
// final exact top-40 from 48 candidates (ties -> lower index)
// ---------------------------------------------------------------------------
__global__ void select_kernel() {
    int b = threadIdx.x;
    if (b >= Bb) return;
    float sc[KSEL]; int id[KSEL];
    for (int i = 0; i < KSEL; i++) {
        sc[i] = g_exact[b * KSEL + i];
        id[i] = g_cand [b * KSEL + i];
    }
    for (int sel = 0; sel < KTOK; sel++) {
        int best = sel;
        for (int i = sel + 1; i < KSEL; i++)
            if (sc[i] > sc[best] || (sc[i] == sc[best] && id[i] < id[best])) best = i;
        float tv = sc[sel]; sc[sel] = sc[best]; sc[best] = tv;
        int   ti = id[sel]; id[sel] = id[best]; id[best] = ti;
        g_idx[b * KTOK + sel] = id[sel];
    }
}

// ---------------------------------------------------------------------------
// gather tokens + indices into d_out
// ---------------------------------------------------------------------------
__global__ void __launch_bounds__(192)
gather_kernel(const float* __restrict__ features, float* __restrict__ out,
              long long out_size) {
    const int blk = blockIdx.x;
    const int b   = blk / KTOK;
    const int tok = g_idx[blk];
    const int t   = threadIdx.x;
    long long base = (long long)blk * Dd;
    if (base + (t + 1) * 4 <= out_size) {
        const float4* src = (const float4*)(features + ((size_t)b * Ss + tok) * Dd);
        ((float4*)(out + base))[t] = src[t];
    }
    if (t == 0) {
        long long pos = (long long)Bb * KTOK * Dd + blk;
        if (pos < out_size) out[pos] = (float)tok;
    }
}

__global__ void fill_zero_kernel(float* __restrict__ out, long long start, long long end) {
    long long i = start + blockIdx.x * (long long)blockDim.x + threadIdx.x;
    if (i < end) out[i] = 0.f;
}

// ---------------------------------------------------------------------------
extern "C" void kernel_launch(void* const* d_in, const int* in_sizes, int n_in,
                              void* d_out, int out_size) {
    const float* features = (const float*)d_in[0];
    const float* W1       = (const float*)d_in[1];
    const float* b1       = (const float*)d_in[2];
    const float* ln_gamma = (const float*)d_in[3];
    const float* ln_beta  = (const float*)d_in[4];
    const float* W2       = (const float*)d_in[5];
    const float* b2       = (const float*)d_in[6];
    float* out = (float*)d_out;

    cudaFuncSetAttribute(gemmscore_kernel,
                         cudaFuncAttributeMaxDynamicSharedMemorySize, SMEM_FUSED);
    cudaFuncSetAttribute(rescore_gemm_kernel,
                         cudaFuncAttributeMaxDynamicSharedMemorySize, SMEM_RGEMM);

    convw_kernel<<<(Dd * Hh + 255) / 256, 256>>>(W1);

    gemmscore_kernel<<<Mtot / GBM, 256, SMEM_FUSED>>>(
        features, b1, ln_gamma, ln_beta, W2, b2);

    topk_kernel<<<Bb, 256>>>();
    rescore_gemm_kernel<<<256, 384, SMEM_RGEMM>>>(features, b1);
    rescore_ln_kernel<<<Bb * KSEL / 8, 256>>>(ln_gamma, ln_beta, W2, b2);
    select_kernel<<<1, Bb>>>();
    gather_kernel<<<Bb * KTOK, 192>>>(features, out, (long long)out_size);

    long long written = (long long)Bb * KTOK * Dd + (long long)Bb * KTOK;
    if ((long long)out_size > written) {
        long long n = (long long)out_size - written;
        int blocks = (int)((n + 255) / 256);
        fill_zero_kernel<<<blocks, 256>>>(out, written, (long long)out_size);
    }
}

// round 6
// speedup vs baseline: 3.7569x; 1.0297x over previous
#include <cuda_runtime.h>
#include <cuda_bf16.h>
#include <math.h>
#include <stdint.h>

// Problem shape (fixed)
#define Bb   16
#define Ss   4096
#define Dd   768
#define Hh   384
#define KTOK 40
#define KSEL 48
#define Mtot (Bb * Ss)   // 65536

// ---------------------------------------------------------------------------
// Device scratch
// ---------------------------------------------------------------------------
__device__ __nv_bfloat16 g_Wt [(size_t)Hh * Dd];  // W1^T bf16 [n][k]
__device__ float         g_Wtf[(size_t)Hh * Dd];  // W1^T f32  [n][k] (exact)
__device__ float         g_scores[Mtot];
__device__ float         g_hex[(size_t)Bb * KSEL * Hh];  // exact h for candidates
__device__ int           g_cand[Bb * KSEL];
__device__ float         g_exact[Bb * KSEL];
__device__ int           g_idx[Bb * KTOK];

// ---------------------------------------------------------------------------
// helpers
// ---------------------------------------------------------------------------
__device__ __forceinline__ uint32_t smem_u32(const void* p) {
    uint32_t a;
    asm("{ .reg .u64 t; cvta.to.shared.u64 t, %1; cvt.u32.u64 %0, t; }"
        : "=r"(a) : "l"(p));
    return a;
}
__device__ __forceinline__ void cp16(uint32_t saddr, const void* gptr) {
    asm volatile("cp.async.cg.shared.global [%0], [%1], 16;"
                 :: "r"(saddr), "l"(gptr));
}
__device__ __forceinline__ void mma_bf16(float* c, const uint32_t* a,
                                         uint32_t b0, uint32_t b1) {
    asm volatile(
        "mma.sync.aligned.m16n8k16.row.col.f32.bf16.bf16.f32 "
        "{%0,%1,%2,%3}, {%4,%5,%6,%7}, {%8,%9}, {%0,%1,%2,%3};"
        : "+f"(c[0]), "+f"(c[1]), "+f"(c[2]), "+f"(c[3])
        : "r"(a[0]), "r"(a[1]), "r"(a[2]), "r"(a[3]), "r"(b0), "r"(b1));
}
#define LDSM4(r, addr)                                                         \
    asm volatile("ldmatrix.sync.aligned.m8n8.x4.shared.b16 "                   \
                 "{%0,%1,%2,%3}, [%4];"                                        \
                 : "=r"((r)[0]), "=r"((r)[1]), "=r"((r)[2]), "=r"((r)[3])      \
                 : "r"(addr))
// pack two f32 -> bf16x2 (low = x, high = y)
__device__ __forceinline__ uint32_t cvtpack(float x, float y) {
    uint32_t r;
    asm("cvt.rn.bf16x2.f32 %0, %1, %2;" : "=r"(r) : "f"(y), "f"(x));
    return r;
}

// ---------------------------------------------------------------------------
// Kernel 0: convert + transpose W1 [768,384] f32 -> g_Wt (bf16), g_Wtf (f32)
// ---------------------------------------------------------------------------
__global__ void convw_kernel(const float* __restrict__ W1) {
    int i = blockIdx.x * blockDim.x + threadIdx.x;
    if (i >= Dd * Hh) return;
    int k = i / Hh, n = i % Hh;
    float v = W1[i];
    g_Wt [(size_t)n * Dd + k] = __float2bfloat16_rn(v);
    g_Wtf[(size_t)n * Dd + k] = v;
}

// ---------------------------------------------------------------------------
// Fused GEMM + score kernel.  CTA: 64 tokens x H=384, K in 24 chunks of 32.
//   256 threads = 8 warps (2M x 4N), warp tile 32x96, mma m16n8k16 bf16.
//   A staged fp32 (cp.async), bulk-converted to bf16 each chunk; fragments
//   loaded with ldmatrix.x4 for both A and B.  2 CTAs/SM.
// ---------------------------------------------------------------------------
#define GBM 64
#define GBK 32
#define NCH (Dd / GBK)          // 24
#define APITCH 176              // f32 staging pitch (stride 12 mod 32 words)
#define ABPITCH 80              // bf16 A pitch
#define BPITCH 80               // bf16 B pitch
#define ABUF (GBM * APITCH)             // 11264
#define ABBUF (GBM * ABPITCH)           // 5120
#define BBUF (Hh * BPITCH)              // 30720
#define OFF_AB (2 * ABUF)               // 22528
#define OFF_B (OFF_AB + ABBUF)          // 27648
#define SMEM_FUSED (OFF_B + 2 * BBUF)   // 89088
#define EPITCH 388

__global__ void __launch_bounds__(256, 2)
gemmscore_kernel(const float* __restrict__ A,  const float* __restrict__ b1,
                 const float* __restrict__ gamma, const float* __restrict__ beta,
                 const float* __restrict__ W2, const float* __restrict__ b2) {
    extern __shared__ char smem[];
    const uint32_t sb = smem_u32(smem);
    const int tid  = threadIdx.x;
    const int lane = tid & 31, wid = tid >> 5;
    const int wm = wid >> 2, wn = wid & 3;       // 2 x 4 warp grid
    const int m0 = blockIdx.x * GBM;
    const int qt = lane & 3, rt = lane >> 2;

    float acc[2][12][4];
    #pragma unroll
    for (int mi = 0; mi < 2; mi++)
        #pragma unroll
        for (int ni = 0; ni < 12; ni++)
            #pragma unroll
            for (int j = 0; j < 4; j++) acc[mi][ni][j] = 0.f;

    // cp.async lane mappings
    const int ar = tid >> 3, aj = tid & 7;           // A: 512 chunks, 2/thread
    const int ar2 = (tid + 256) >> 3, aj2 = (tid + 256) & 7;

    // ldmatrix lane-address components
    const int lmat = lane >> 3, lrin = lane & 7;
    // A: matrices 0/1 = rows +0/+8 (k lo), 2/3 = rows +0/+8 (k hi)
    const int a_row = (lmat & 1) * 8 + lrin;
    const int a_khi = (lmat >> 1) * 8;
    // B: matrices 0/1 = k lo/hi (rows +0), 2/3 = k lo/hi (rows +8)
    const int b_row = (lmat >> 1) * 8 + lrin;
    const int b_khi = (lmat & 1) * 8;

    // convert-pass mapping: 2048 bf16 elems, 8 per thread
    const int cvr = tid >> 2, cvs = tid & 3;

    // ---- preload chunk 0 ----
    cp16(sb + ar  * APITCH + aj  * 16, A + (size_t)(m0 + ar)  * Dd + aj  * 4);
    cp16(sb + ar2 * APITCH + aj2 * 16, A + (size_t)(m0 + ar2) * Dd + aj2 * 4);
    #pragma unroll
    for (int i = 0; i < 6; i++) {
        int f = tid + i * 256;
        int n = f >> 2, j = f & 3;
        cp16(sb + OFF_B + n * BPITCH + j * 16, g_Wt + (size_t)n * Dd + j * 8);
    }
    asm volatile("cp.async.commit_group;");

    for (int c = 0; c < NCH; c++) {
        const int s = c & 1;

        if (c + 1 < NCH) {
            const int s1 = (c + 1) & 1;
            const int ko = (c + 1) * GBK;
            cp16(sb + s1 * ABUF + ar  * APITCH + aj  * 16,
                 A + (size_t)(m0 + ar)  * Dd + ko + aj  * 4);
            cp16(sb + s1 * ABUF + ar2 * APITCH + aj2 * 16,
                 A + (size_t)(m0 + ar2) * Dd + ko + aj2 * 4);
            #pragma unroll
            for (int i = 0; i < 6; i++) {
                int f = tid + i * 256;
                int n = f >> 2, j = f & 3;
                cp16(sb + OFF_B + s1 * BBUF + n * BPITCH + j * 16,
                     g_Wt + (size_t)n * Dd + ko + j * 8);
            }
            asm volatile("cp.async.commit_group;");
            asm volatile("cp.async.wait_group 1;");
        } else {
            asm volatile("cp.async.wait_group 0;");
        }
        __syncthreads();

        // ---- convert A chunk f32 -> bf16 (2048 elems, 8/thread) ----
        {
            const char* src = smem + s * ABUF + cvr * APITCH + cvs * 32;
            float4 v0 = *(const float4*)(src);
            float4 v1 = *(const float4*)(src + 16);
            uint4 p;
            p.x = cvtpack(v0.x, v0.y);
            p.y = cvtpack(v0.z, v0.w);
            p.z = cvtpack(v1.x, v1.y);
            p.w = cvtpack(v1.z, v1.w);
            *(uint4*)(smem + OFF_AB + cvr * ABPITCH + cvs * 16) = p;
        }
        __syncthreads();

        const uint32_t pb = sb + OFF_B + s * BBUF;
        const uint32_t pab = sb + OFF_AB;

        #pragma unroll
        for (int ks = 0; ks < 2; ks++) {
            const int kb = ks * 16;
            uint32_t afr[2][4];
            #pragma unroll
            for (int mi = 0; mi < 2; mi++) {
                uint32_t aaddr = pab + (wm * 32 + mi * 16 + a_row) * ABPITCH
                               + (kb + a_khi) * 2;
                LDSM4(afr[mi], aaddr);
            }
            #pragma unroll
            for (int np = 0; np < 6; np++) {
                uint32_t bfr[4];
                uint32_t baddr = pb + (wn * 96 + np * 16 + b_row) * BPITCH
                               + (kb + b_khi) * 2;
                LDSM4(bfr, baddr);
                mma_bf16(acc[0][2 * np],     afr[0], bfr[0], bfr[1]);
                mma_bf16(acc[0][2 * np + 1], afr[0], bfr[2], bfr[3]);
                mma_bf16(acc[1][2 * np],     afr[1], bfr[0], bfr[1]);
                mma_bf16(acc[1][2 * np + 1], afr[1], bfr[2], bfr[3]);
            }
        }
        __syncthreads();
    }

    // ---- epilogue: two passes of 32 rows; LN + GELU + W2 + sigmoid ----
    float* eb = (float*)smem;
    float gm[12], bt[12], w2r[12], b1r[12];
    #pragma unroll
    for (int i = 0; i < 12; i++) {
        int j = lane + 32 * i;
        gm[i]  = gamma[j];
        bt[i]  = beta[j];
        w2r[i] = W2[j];
        b1r[i] = b1[j];
    }
    const float b2v = b2[0];

    #pragma unroll
    for (int p = 0; p < 2; p++) {
        if (wm == p) {
            #pragma unroll
            for (int mi = 0; mi < 2; mi++) {
                #pragma unroll
                for (int ni = 0; ni < 12; ni++) {
                    int rl  = mi * 16 + rt;
                    int col = wn * 96 + ni * 8 + 2 * qt;
                    *(float2*)&eb[rl * EPITCH + col] =
                        make_float2(acc[mi][ni][0], acc[mi][ni][1]);
                    *(float2*)&eb[(rl + 8) * EPITCH + col] =
                        make_float2(acc[mi][ni][2], acc[mi][ni][3]);
                }
            }
        }
        __syncthreads();
        #pragma unroll
        for (int rr = 0; rr < 4; rr++) {
            const int rowl = wid * 4 + rr;
            float x[12];
            float sum = 0.f;
            #pragma unroll
            for (int i = 0; i < 12; i++) {
                x[i] = eb[rowl * EPITCH + lane + 32 * i] + b1r[i];
                sum += x[i];
            }
            #pragma unroll
            for (int o = 16; o > 0; o >>= 1) sum += __shfl_xor_sync(0xffffffffu, sum, o);
            const float mu = sum * (1.0f / Hh);
            float sq = 0.f;
            #pragma unroll
            for (int i = 0; i < 12; i++) { float d = x[i] - mu; sq += d * d; }
            #pragma unroll
            for (int o = 16; o > 0; o >>= 1) sq += __shfl_xor_sync(0xffffffffu, sq, o);
            const float rstd = 1.0f / sqrtf(sq * (1.0f / Hh) + 1e-5f);
            float dot = 0.f;
            #pragma unroll
            for (int i = 0; i < 12; i++) {
                float xn = (x[i] - mu) * rstd * gm[i] + bt[i];
                float ge = 0.5f * xn * (1.0f + erff(xn * 0.70710678118654752f));
                dot += ge * w2r[i];
            }
            #pragma unroll
            for (int o = 16; o > 0; o >>= 1) dot += __shfl_xor_sync(0xffffffffu, dot, o);
            if (lane == 0)
                g_scores[m0 + p * 32 + rowl] = 1.0f / (1.0f + expf(-(dot + b2v)));
        }
        __syncthreads();
    }
}

// ---------------------------------------------------------------------------
// top-48 candidates per batch, u64-key warp-shfl argmax (ties -> lower index)
// ---------------------------------------------------------------------------
__device__ __forceinline__ unsigned long long score_key(float f, int i) {
    uint32_t b = __float_as_uint(f);
    uint32_t flip = (b & 0x80000000u) ? ~b : (b | 0x80000000u);
    return ((unsigned long long)flip << 32) | (uint32_t)(Ss - 1 - i);
}

__global__ void __launch_bounds__(256)
topk_kernel() {
    __shared__ float s[Ss];
    __shared__ unsigned long long wred[8];
    const int b = blockIdx.x;
    const int t = threadIdx.x;
    const int lane = t & 31, wid = t >> 5;

    for (int i = t; i < Ss; i += 256) s[i] = g_scores[b * Ss + i];
    __syncthreads();

    for (int sel = 0; sel < KSEL; sel++) {
        unsigned long long best = 0ull;
        #pragma unroll
        for (int u = 0; u < Ss / 256; u++) {
            int i = t + u * 256;
            unsigned long long k = score_key(s[i], i);
            if (k > best) best = k;
        }
        #pragma unroll
        for (int o = 16; o > 0; o >>= 1) {
            unsigned long long ok = __shfl_xor_sync(0xffffffffu, best, o);
            if (ok > best) best = ok;
        }
        if (lane == 0) wred[wid] = best;
        __syncthreads();
        if (t < 8) {
            unsigned long long v = wred[t];
            #pragma unroll
            for (int o = 4; o > 0; o >>= 1) {
                unsigned long long ov = __shfl_xor_sync(0xffu, v, o, 8);
                if (ov > v) v = ov;
            }
            if (t == 0) {
                int idx = Ss - 1 - (int)(v & 0xFFFFFFFFu);
                g_cand[b * KSEL + sel] = idx;
                s[idx] = -1.0f;
            }
        }
        __syncthreads();
    }
}

// ---------------------------------------------------------------------------
// rescore GEMM: exact fp32 h for 768 candidates.
//   256 blocks = (batch 16) x (token-group 4) x (col-quarter 4).
//   384 threads = (k-eighth 8) x (col-pair 48): 2 cols/thread, K/8 each.
// ---------------------------------------------------------------------------
__global__ void __launch_bounds__(384)
rescore_gemm_kernel(const float* __restrict__ features, const float* __restrict__ b1) {
    extern __shared__ char rsm[];
    float* feat = (float*)rsm;                 // 12 x 768
    float* part = feat + 12 * Dd;              // 8 x 12 x 96

    const int blk = blockIdx.x;
    const int b   = blk >> 4;
    const int grp = (blk >> 2) & 3;
    const int cq  = blk & 3;
    const int t = threadIdx.x;
    const int kq = t / 48;                     // 0..7
    const int cp = t % 48;                     // col pair 0..47
    const int c0l = cp * 2;                    // local col 0..94
    const int col0 = cq * 96 + c0l;

    const int cbase = b * KSEL + grp * 12;
    for (int j = 0; j < 12; j++) {
        int tok = g_cand[cbase + j];
        const float* src = features + ((size_t)b * Ss + tok) * Dd;
        for (int k = t; k < Dd; k += 384) feat[j * Dd + k] = src[k];
    }
    __syncthreads();

    float acc[12][2];
    #pragma unroll
    for (int j = 0; j < 12; j++) { acc[j][0] = 0.f; acc[j][1] = 0.f; }

    const float4* w0p = (const float4*)(g_Wtf + (size_t)col0 * Dd) + kq * 24;
    const float4* w1p = (const float4*)(g_Wtf + (size_t)(col0 + 1) * Dd) + kq * 24;
    #pragma unroll 4
    for (int it = 0; it < 24; it++) {
        float4 w0 = w0p[it];
        float4 w1 = w1p[it];
        #pragma unroll
        for (int j = 0; j < 12; j++) {
            float4 f = *((const float4*)(feat + j * Dd + kq * 96) + it);
            acc[j][0] = fmaf(f.x, w0.x, fmaf(f.y, w0.y,
                        fmaf(f.z, w0.z, fmaf(f.w, w0.w, acc[j][0]))));
            acc[j][1] = fmaf(f.x, w1.x, fmaf(f.y, w1.y,
                        fmaf(f.z, w1.z, fmaf(f.w, w1.w, acc[j][1]))));
        }
    }
    #pragma unroll
    for (int j = 0; j < 12; j++) {
        part[(kq * 12 + j) * 96 + c0l]     = acc[j][0];
        part[(kq * 12 + j) * 96 + c0l + 1] = acc[j][1];
    }
    __syncthreads();

    for (int idx = t; idx < 12 * 96; idx += 384) {
        int j = idx / 96, c = idx % 96;
        float h = b1[cq * 96 + c];
        #pragma unroll
        for (int q = 0; q < 8; q++) h += part[(q * 12 + j) * 96 + c];
        g_hex[(size_t)(cbase + j) * Hh + cq * 96 + c] = h;
    }
}
#define SMEM_RGEMM ((12 * Dd + 8 * 12 * 96) * 4)   // 73728 B

// ---------------------------------------------------------------------------
// rescore LN: warp per candidate token -> exact score
// ---------------------------------------------------------------------------
__global__ void __launch_bounds__(256)
rescore_ln_kernel(const float* __restrict__ gamma, const float* __restrict__ beta,
                  const float* __restrict__ W2, const float* __restrict__ b2) {
    const int lane = threadIdx.x & 31, wid = threadIdx.x >> 5;
    const int cand = blockIdx.x * 8 + wid;     // 0..767
    const float* row = g_hex + (size_t)cand * Hh;

    float x[12];
    float sum = 0.f;
    #pragma unroll
    for (int i = 0; i < 12; i++) { x[i] = row[lane + 32 * i]; sum += x[i]; }
    #pragma unroll
    for (int o = 16; o > 0; o >>= 1) sum += __shfl_xor_sync(0xffffffffu, sum, o);
    const float mu = sum * (1.0f / Hh);
    float sq = 0.f;
    #pragma unroll
    for (int i = 0; i < 12; i++) { float d = x[i] - mu; sq += d * d; }
    #pragma unroll
    for (int o = 16; o > 0; o >>= 1) sq += __shfl_xor_sync(0xffffffffu, sq, o);
    const float rstd = 1.0f / sqrtf(sq * (1.0f / Hh) + 1e-5f);
    float dot = 0.f;
    #pragma unroll
    for (int i = 0; i < 12; i++) {
        float xn = (x[i] - mu) * rstd * gamma[lane + 32 * i] + beta[lane + 32 * i];
        float ge = 0.5f * xn * (1.0f + erff(xn * 0.70710678118654752f));
        dot += ge * W2[lane + 32 * i];
    }
    #pragma unroll
    for (int o = 16; o > 0; o >>= 1) dot += __shfl_xor_sync(0xffffffffu, dot, o);
    if (lane == 0)
        g_exact[cand] = 1.0f / (1.0f + expf(-(dot + b2[0])));
}

// ---------------------------------------------------------------------------
// final exact top-40 from 48 candidates (ties -> lower index)
// ---------------------------------------------------------------------------
__global__ void select_kernel() {
    int b = threadIdx.x;
    if (b >= Bb) return;
    float sc[KSEL]; int id[KSEL];
    for (int i = 0; i < KSEL; i++) {
        sc[i] = g_exact[b * KSEL + i];
        id[i] = g_cand [b * KSEL + i];
    }
    for (int sel = 0; sel < KTOK; sel++) {
        int best = sel;
        for (int i = sel + 1; i < KSEL; i++)
            if (sc[i] > sc[best] || (sc[i] == sc[best] && id[i] < id[best])) best = i;
        float tv = sc[sel]; sc[sel] = sc[best]; sc[best] = tv;
        int   ti = id[sel]; id[sel] = id[best]; id[best] = ti;
        g_idx[b * KTOK + sel] = id[sel];
    }
}

// ---------------------------------------------------------------------------
// gather tokens + indices into d_out
// ---------------------------------------------------------------------------
__global__ void __launch_bounds__(192)
gather_kernel(const float* __restrict__ features, float* __restrict__ out,
              long long out_size) {
    const int blk = blockIdx.x;
    const int b   = blk / KTOK;
    const int tok = g_idx[blk];
    const int t   = threadIdx.x;
    long long base = (long long)blk * Dd;
    if (base + (t + 1) * 4 <= out_size) {
        const float4* src = (const float4*)(features + ((size_t)b * Ss + tok) * Dd);
        ((float4*)(out + base))[t] = src[t];
    }
    if (t == 0) {
        long long pos = (long long)Bb * KTOK * Dd + blk;
        if (pos < out_size) out[pos] = (float)tok;
    }
}

__global__ void fill_zero_kernel(float* __restrict__ out, long long start, long long end) {
    long long i = start + blockIdx.x * (long long)blockDim.x + threadIdx.x;
    if (i < end) out[i] = 0.f;
}

// ---------------------------------------------------------------------------
extern "C" void kernel_launch(void* const* d_in, const int* in_sizes, int n_in,
                              void* d_out, int out_size) {
    const float* features = (const float*)d_in[0];
    const float* W1       = (const float*)d_in[1];
    const float* b1       = (const float*)d_in[2];
    const float* ln_gamma = (const float*)d_in[3];
    const float* ln_beta  = (const float*)d_in[4];
    const float* W2       = (const float*)d_in[5];
    const float* b2       = (const float*)d_in[6];
    float* out = (float*)d_out;

    cudaFuncSetAttribute(gemmscore_kernel,
                         cudaFuncAttributeMaxDynamicSharedMemorySize, SMEM_FUSED);
    cudaFuncSetAttribute(rescore_gemm_kernel,
                         cudaFuncAttributeMaxDynamicSharedMemorySize, SMEM_RGEMM);

    convw_kernel<<<(Dd * Hh + 255) / 256, 256>>>(W1);

    gemmscore_kernel<<<Mtot / GBM, 256, SMEM_FUSED>>>(
        features, b1, ln_gamma, ln_beta, W2, b2);

    topk_kernel<<<Bb, 256>>>();
    rescore_gemm_kernel<<<256, 384, SMEM_RGEMM>>>(features, b1);
    rescore_ln_kernel<<<Bb * KSEL / 8, 256>>>(ln_gamma, ln_beta, W2, b2);
    select_kernel<<<1, Bb>>>();
    gather_kernel<<<Bb * KTOK, 192>>>(features, out, (long long)out_size);

    long long written = (long long)Bb * KTOK * Dd + (long long)Bb * KTOK;
    if ((long long)out_size > written) {
        long long n = (long long)out_size - written;
        int blocks = (int)((n + 255) / 256);
        fill_zero_kernel<<<blocks, 256>>>(out, written, (long long)out_size);
    }
}